// round 14
// baseline (speedup 1.0000x reference)
#include <cuda_runtime.h>
#include <cuda_bf16.h>
#include <cstdint>

#define N_NODES  131072
#define N_PER    1024
#define B_GRAPHS 128
#define N_EDGE   2097152
#define EPG      (N_EDGE / B_GRAPHS)
#define HID      128
#define IN_CH    14
#define K_POOL   30
#define CONV_T   26
#define FEAT_LEN 832

typedef unsigned long long u64;
#define FMA2(acc, a, b) \
    asm("fma.rn.f32x2 %0, %1, %2, %0;" : "+l"(acc) : "l"(a), "l"(b))
union F4 { float4 f; u64 d[2]; };

// ---------------- scratch (device-only) ----------------
__device__ int    g_cnt[N_NODES];
__device__ int    g_rowstart[N_NODES];
__device__ float  g_deginv[N_NODES];
__device__ int    g_csrc[N_EDGE];
__device__ float4 g_hA[N_NODES * HID / 4];
__device__ float4 g_hB[N_NODES * HID / 4];
__device__ float4 g_w4[4 * 32 * HID];      // chunk-packed k-major wl2,wr2,wl3,wr3
__device__ float  g_wt1[2 * IN_CH * HID];  // k-major layer1 weights
__device__ int    g_idx64;

// ---------------- prep ----------------
__global__ __launch_bounds__(256) void k_prep(
    const unsigned int* ei,
    const float* __restrict__ wl1, const float* __restrict__ wr1,
    const float* __restrict__ wl2, const float* __restrict__ wr2,
    const float* __restrict__ wl3, const float* __restrict__ wr3) {
    int bid = blockIdx.x, tid = threadIdx.x;
    if (bid < 256) {
        int t = bid * 256 + tid;
        int w = t >> 14;
        int rem = t & 16383;                  // j*128 + k
        int j = rem >> 7, k = rem & 127;
        const float* src = (w == 0) ? wl2 : (w == 1) ? wr2 : (w == 2) ? wl3 : wr3;
        ((float*)g_w4)[w * 16384 + (k >> 2) * 512 + j * 4 + (k & 3)] = src[rem];
    } else if (bid < 270) {
        int t = (bid - 256) * 256 + tid;
        if (t < 2 * IN_CH * HID) {
            int m = t / (IN_CH * HID);
            int rem = t % (IN_CH * HID);
            int j = rem / IN_CH, k = rem % IN_CH;
            g_wt1[m * IN_CH * HID + k * HID + j] = (m == 0 ? wl1 : wr1)[rem];
        }
    } else if (tid == 0) {
        int all0 = 1;
        for (int i = 0; i < 16; i++)
            if (ei[2 * i + 1] != 0u) all0 = 0;
        g_idx64 = all0;
    }
}

// ---------------- per-graph CSR build ----------------
__global__ __launch_bounds__(1024) void k_csr(const void* ei) {
    __shared__ int cnt_s[N_PER];
    __shared__ int cur_s[N_PER];
    __shared__ int wsum[32];
    int g = blockIdx.x, t = threadIdx.x;
    int lane = t & 31, warp = t >> 5;
    int ebase = g * EPG, nbase = g * N_PER;
    int idx64 = g_idx64;

    cnt_s[t] = 0;
    __syncthreads();
    if (idx64) {
        const long long* p = (const long long*)ei;
#pragma unroll 4
        for (int i = t; i < EPG; i += 1024)
            atomicAdd(&cnt_s[(int)p[N_EDGE + ebase + i] - nbase], 1);
    } else {
        const int* p = (const int*)ei;
#pragma unroll 4
        for (int i = t; i < EPG; i += 1024)
            atomicAdd(&cnt_s[p[N_EDGE + ebase + i] - nbase], 1);
    }
    __syncthreads();
    int c = cnt_s[t], v = c;
#pragma unroll
    for (int o = 1; o < 32; o <<= 1) {
        int u = __shfl_up_sync(0xffffffffu, v, o);
        if (lane >= o) v += u;
    }
    if (lane == 31) wsum[warp] = v;
    __syncthreads();
    if (warp == 0) {
        int w = wsum[lane];
#pragma unroll
        for (int o = 1; o < 32; o <<= 1) {
            int u = __shfl_up_sync(0xffffffffu, w, o);
            if (lane >= o) w += u;
        }
        wsum[lane] = w;
    }
    __syncthreads();
    int start_local = v + (warp > 0 ? wsum[warp - 1] : 0) - c;
    g_rowstart[nbase + t] = ebase + start_local;
    g_cnt[nbase + t] = c;
    g_deginv[nbase + t] = c > 0 ? 1.0f / (float)c : 0.0f;
    cur_s[t] = start_local;
    __syncthreads();
    if (idx64) {
        const long long* p = (const long long*)ei;
#pragma unroll 4
        for (int i = t; i < EPG; i += 1024) {
            int s = (int)p[ebase + i], d = (int)p[N_EDGE + ebase + i] - nbase;
            g_csrc[ebase + atomicAdd(&cur_s[d], 1)] = s;
        }
    } else {
        const int* p = (const int*)ei;
#pragma unroll 4
        for (int i = t; i < EPG; i += 1024) {
            int s = p[ebase + i], d = p[N_EDGE + ebase + i] - nbase;
            g_csrc[ebase + atomicAdd(&cur_s[d], 1)] = s;
        }
    }
}

// ---------------- layer 1 fused ----------------
__global__ __launch_bounds__(256, 6) void k_layer1(
    const float* __restrict__ x, const float* __restrict__ b) {
    __shared__ float a_s[32 * IN_CH];
    __shared__ float x_s[32 * IN_CH];
    int nb = blockIdx.x * 32, tid = threadIdx.x;
    int warp = tid >> 5, lane = tid & 31;

    for (int i = tid; i < 32 * IN_CH; i += 256)
        x_s[i] = x[(size_t)(nb + i / IN_CH) * IN_CH + i % IN_CH];

    int hw = lane >> 4;
    int ch = lane & 15;
    for (int q = 0; q < 4; q++) {
        int node = nb + warp * 4 + q;
        int start = g_rowstart[node];
        int deg = g_cnt[node];
        float acc = 0.0f;
        if (ch < IN_CH) {
            for (int j = hw; j < deg; j += 2)
                acc += x[(size_t)g_csrc[start + j] * IN_CH + ch];
        }
        acc += __shfl_down_sync(0xffffffffu, acc, 16);
        if (lane < IN_CH)
            a_s[(warp * 4 + q) * IN_CH + lane] = acc * g_deginv[node];
    }
    __syncthreads();

    int j = tid & 127, half = tid >> 7;
    const float* wlt = g_wt1 + j;
    const float* wrt = g_wt1 + IN_CH * HID + j;
    float acc[16], bj = b[j];
#pragma unroll
    for (int n = 0; n < 16; n++) acc[n] = bj;
    const float* as = a_s + half * 16 * IN_CH;
    const float* xs = x_s + half * 16 * IN_CH;
    for (int k = 0; k < IN_CH; k++) {
        float wlv = wlt[k * HID], wrv = wrt[k * HID];
#pragma unroll
        for (int n = 0; n < 16; n++)
            acc[n] += as[n * IN_CH + k] * wlv + xs[n * IN_CH + k] * wrv;
    }
    float* hout = (float*)g_hA;
#pragma unroll
    for (int n = 0; n < 16; n++)
        hout[(size_t)(nb + half * 16 + n) * HID + j] = fmaxf(acc[n], 0.0f);
}

// ---------------- fused SAGE layer: 64-node CTA, 8-way gather, f32x2 dense ----------
// Dynamic smem: a_s4[2048] (agg tile, 32KB) + p_s4[2048] (self tile, 32KB).
// Dense: thread = 2 j {jj, jj+64} x 16 nodes; halves per-node weight wavefronts.
__global__ __launch_bounds__(256, 2) void k_layer(const float* __restrict__ b, int sel) {
    extern __shared__ float4 s_dyn[];
    float4* a_s4 = s_dyn;          // [64][32]
    float4* p_s4 = s_dyn + 2048;   // [64][32]
    int nb = blockIdx.x * 64, tid = threadIdx.x;
    int warp = tid >> 5, lane = tid & 31;

    const float4* h4 = sel ? g_hB : g_hA;
    float* hout      = sel ? (float*)g_hA : (float*)g_hB;
    const float4* wl4 = g_w4 + sel * 8192;
    const float4* wr4 = wl4 + 4096;

#pragma unroll
    for (int i = 0; i < 8; i++)
        p_s4[tid + i * 256] = h4[(size_t)nb * 32 + tid + i * 256];

    // aggregation: warp handles 8 nodes; lane owns a float4 column; 8-way MLP
    for (int q = 0; q < 8; q++) {
        int node = nb + warp * 8 + q;
        int start = g_rowstart[node];
        int deg = g_cnt[node];
        float4 a0 = make_float4(0.f, 0.f, 0.f, 0.f);
        float4 a1 = a0, a2 = a0, a3 = a0, a4v = a0, a5 = a0, a6 = a0, a7 = a0;
        int j = 0;
        for (; j + 8 <= deg; j += 8) {
            float4 v0 = h4[(size_t)g_csrc[start + j] * 32 + lane];
            float4 v1 = h4[(size_t)g_csrc[start + j + 1] * 32 + lane];
            float4 v2 = h4[(size_t)g_csrc[start + j + 2] * 32 + lane];
            float4 v3 = h4[(size_t)g_csrc[start + j + 3] * 32 + lane];
            float4 v4 = h4[(size_t)g_csrc[start + j + 4] * 32 + lane];
            float4 v5 = h4[(size_t)g_csrc[start + j + 5] * 32 + lane];
            float4 v6 = h4[(size_t)g_csrc[start + j + 6] * 32 + lane];
            float4 v7 = h4[(size_t)g_csrc[start + j + 7] * 32 + lane];
            a0.x += v0.x; a0.y += v0.y; a0.z += v0.z; a0.w += v0.w;
            a1.x += v1.x; a1.y += v1.y; a1.z += v1.z; a1.w += v1.w;
            a2.x += v2.x; a2.y += v2.y; a2.z += v2.z; a2.w += v2.w;
            a3.x += v3.x; a3.y += v3.y; a3.z += v3.z; a3.w += v3.w;
            a4v.x += v4.x; a4v.y += v4.y; a4v.z += v4.z; a4v.w += v4.w;
            a5.x += v5.x; a5.y += v5.y; a5.z += v5.z; a5.w += v5.w;
            a6.x += v6.x; a6.y += v6.y; a6.z += v6.z; a6.w += v6.w;
            a7.x += v7.x; a7.y += v7.y; a7.z += v7.z; a7.w += v7.w;
        }
        for (; j < deg; j++) {
            float4 v0 = h4[(size_t)g_csrc[start + j] * 32 + lane];
            a0.x += v0.x; a0.y += v0.y; a0.z += v0.z; a0.w += v0.w;
        }
        float dv = g_deginv[node];
        a0.x = (a0.x + a1.x + a2.x + a3.x + a4v.x + a5.x + a6.x + a7.x) * dv;
        a0.y = (a0.y + a1.y + a2.y + a3.y + a4v.y + a5.y + a6.y + a7.y) * dv;
        a0.z = (a0.z + a1.z + a2.z + a3.z + a4v.z + a5.z + a6.z + a7.z) * dv;
        a0.w = (a0.w + a1.w + a2.w + a3.w + a4v.w + a5.w + a6.w + a7.w) * dv;
        a_s4[(warp * 8 + q) * 32 + lane] = a0;
    }
    __syncthreads();

    // dense: 2 output channels {jj, jj+64} x 16 nodes, f32x2, two passes
    int jj = tid & 63;
    int q  = tid >> 6;      // node group: nodes q*16 .. q*16+15
    u64 accA2[16], accB2[16];
#pragma unroll
    for (int n = 0; n < 16; n++) { accA2[n] = 0ull; accB2[n] = 0ull; }

    const float4* a4 = a_s4 + q * 16 * 32;
    const float4* p4 = p_s4 + q * 16 * 32;
    for (int kc = 0; kc < 32; kc++) {
        F4 wA, wB;
        wA.f = wl4[kc * 128 + jj];
        wB.f = wl4[kc * 128 + jj + 64];
#pragma unroll
        for (int n = 0; n < 16; n++) {
            F4 av; av.f = a4[n * 32 + kc];
            FMA2(accA2[n], av.d[0], wA.d[0]);
            FMA2(accA2[n], av.d[1], wA.d[1]);
            FMA2(accB2[n], av.d[0], wB.d[0]);
            FMA2(accB2[n], av.d[1], wB.d[1]);
        }
    }
    for (int kc = 0; kc < 32; kc++) {
        F4 wA, wB;
        wA.f = wr4[kc * 128 + jj];
        wB.f = wr4[kc * 128 + jj + 64];
#pragma unroll
        for (int n = 0; n < 16; n++) {
            F4 pv; pv.f = p4[n * 32 + kc];
            FMA2(accA2[n], pv.d[0], wA.d[0]);
            FMA2(accA2[n], pv.d[1], wA.d[1]);
            FMA2(accB2[n], pv.d[0], wB.d[0]);
            FMA2(accB2[n], pv.d[1], wB.d[1]);
        }
    }

    float bA = b[jj], bB = b[jj + 64];
#pragma unroll
    for (int n = 0; n < 16; n++) {
        float2 rA = *(float2*)&accA2[n];
        float2 rB = *(float2*)&accB2[n];
        size_t row = (size_t)(nb + q * 16 + n) * HID;
        hout[row + jj]      = fmaxf(bA + rA.x + rA.y, 0.0f);
        hout[row + jj + 64] = fmaxf(bB + rB.x + rB.y, 0.0f);
    }
}

// ---------------- fused top-k + conv1d + lin1 + lin2 ----------------
#define TS_PAD 32
__global__ __launch_bounds__(256) void k_topk_head(
    const float* __restrict__ conv_w, const float* __restrict__ conv_b,
    const float* __restrict__ lin1_w, const float* __restrict__ lin1_b,
    const float* __restrict__ lin2_w, const float* __restrict__ lin2_b,
    float* __restrict__ out) {
    __shared__ float vals[N_PER];
    __shared__ unsigned long long wred[8];
    __shared__ int sel[K_POOL];
    __shared__ float top_ts[HID * TS_PAD];
    __shared__ float feat[FEAT_LEN];
    __shared__ float y1[HID];
    const float* h = (const float*)g_hA;
    int g = blockIdx.x, tid = threadIdx.x;
    int warp = tid >> 5, lane = tid & 31;
    size_t base = (size_t)g * N_PER;

    for (int i = tid; i < N_PER; i += 256)
        vals[i] = h[(base + i) * HID + (HID - 1)];
    __syncthreads();
    for (int t = 0; t < K_POOL; t++) {
        unsigned long long best = 0ull;
        for (int i = tid; i < N_PER; i += 256) {
            float v = vals[i];
            if (v >= 0.0f) {
                unsigned long long key =
                    ((unsigned long long)__float_as_uint(v) << 32) |
                    (unsigned long long)(0xFFFFFFFFu - (unsigned)i);
                if (key > best) best = key;
            }
        }
#pragma unroll
        for (int o = 16; o > 0; o >>= 1) {
            unsigned long long other = __shfl_down_sync(0xffffffffu, best, o);
            if (other > best) best = other;
        }
        if (lane == 0) wred[warp] = best;
        __syncthreads();
        if (tid == 0) {
            unsigned long long b0 = wred[0];
#pragma unroll
            for (int w = 1; w < 8; w++)
                if (wred[w] > b0) b0 = wred[w];
            int idx = (int)(0xFFFFFFFFu - (unsigned)(b0 & 0xFFFFFFFFull));
            sel[t] = idx;
            vals[idx] = -1.0f;
        }
        __syncthreads();
    }
    for (int i = tid; i < K_POOL * HID; i += 256) {
        int t = i / HID, c = i % HID;
        top_ts[c * TS_PAD + t] = h[(base + sel[t]) * HID + c];
    }
    __syncthreads();
    for (int m = tid; m < FEAT_LEN; m += 256) {
        int o = m / CONV_T, t = m % CONV_T;
        float acc = conv_b[o];
        const float* wrow = conv_w + (size_t)o * HID * 5;
        for (int c = 0; c < HID; c++) {
            const float* w5 = wrow + c * 5;
            const float* ts = top_ts + c * TS_PAD + t;
#pragma unroll
            for (int tau = 0; tau < 5; tau++)
                acc += ts[tau] * w5[tau];
        }
        feat[m] = fmaxf(acc, 0.0f);
    }
    __syncthreads();
    if (tid < HID) {
        float acc = lin1_b[tid];
        const float* wrow = lin1_w + (size_t)tid * FEAT_LEN;
        for (int k = 0; k < FEAT_LEN; k++) acc += feat[k] * wrow[k];
        y1[tid] = fmaxf(acc, 0.0f);
    }
    __syncthreads();
    if (tid < 4) {
        float acc = lin2_b[tid];
        const float* wrow = lin2_w + tid * HID;
        for (int k = 0; k < HID; k++) acc += y1[k] * wrow[k];
        out[g * 4 + tid] = acc;
    }
}

// ---------------- launcher ----------------
extern "C" void kernel_launch(void* const* d_in, const int* in_sizes, int n_in,
                              void* d_out, int out_size) {
    const float* x      = (const float*)d_in[0];
    const void*  ei     = d_in[1];
    const float* w_l1   = (const float*)d_in[3];
    const float* b_l1   = (const float*)d_in[4];
    const float* w_r1   = (const float*)d_in[5];
    const float* w_l2   = (const float*)d_in[6];
    const float* b_l2   = (const float*)d_in[7];
    const float* w_r2   = (const float*)d_in[8];
    const float* w_l3   = (const float*)d_in[9];
    const float* b_l3   = (const float*)d_in[10];
    const float* w_r3   = (const float*)d_in[11];
    const float* conv_w = (const float*)d_in[12];
    const float* conv_b = (const float*)d_in[13];
    const float* lin1_w = (const float*)d_in[14];
    const float* lin1_b = (const float*)d_in[15];
    const float* lin2_w = (const float*)d_in[16];
    const float* lin2_b = (const float*)d_in[17];
    float* out = (float*)d_out;

    static int smem_set = 0;
    if (!smem_set) {
        cudaFuncSetAttribute(k_layer, cudaFuncAttributeMaxDynamicSharedMemorySize, 65536);
        smem_set = 1;
    }

    k_prep<<<271, 256>>>((const unsigned int*)ei, w_l1, w_r1, w_l2, w_r2, w_l3, w_r3);
    k_csr<<<B_GRAPHS, 1024>>>(ei);
    k_layer1<<<N_NODES / 32, 256>>>(x, b_l1);
    k_layer<<<N_NODES / 64, 256, 65536>>>(b_l2, 0);   // 4th launch -> profiled
    k_layer<<<N_NODES / 64, 256, 65536>>>(b_l3, 1);
    k_topk_head<<<B_GRAPHS, 256>>>(conv_w, conv_b, lin1_w, lin1_b,
                                   lin2_w, lin2_b, out);
}

// round 15
// speedup vs baseline: 1.1215x; 1.1215x over previous
#include <cuda_runtime.h>
#include <cuda_bf16.h>
#include <cstdint>

#define N_NODES  131072
#define N_PER    1024
#define B_GRAPHS 128
#define N_EDGE   2097152
#define EPG      (N_EDGE / B_GRAPHS)
#define HID      128
#define IN_CH    14
#define K_POOL   30
#define CONV_T   26
#define FEAT_LEN 832

typedef unsigned long long u64;
#define FMA2(acc, a, b) \
    asm("fma.rn.f32x2 %0, %1, %2, %0;" : "+l"(acc) : "l"(a), "l"(b))
union F4 { float4 f; u64 d[2]; };

// ---------------- scratch (device-only) ----------------
__device__ int    g_cnt[N_NODES];
__device__ int    g_rowstart[N_NODES];
__device__ float  g_deginv[N_NODES];
__device__ int    g_csrc[N_EDGE];
__device__ float4 g_hA[N_NODES * HID / 4];
__device__ float4 g_hB[N_NODES * HID / 4];
__device__ float4 g_w4[4 * 32 * HID];      // chunk-packed k-major wl2,wr2,wl3,wr3
__device__ float  g_wt1[2 * IN_CH * HID];  // k-major layer1 weights
__device__ int    g_idx64;

// ---------------- prep A: weight repack ----------------
__global__ __launch_bounds__(256) void k_prep_w(
    const float* __restrict__ wl1, const float* __restrict__ wr1,
    const float* __restrict__ wl2, const float* __restrict__ wr2,
    const float* __restrict__ wl3, const float* __restrict__ wr3) {
    int bid = blockIdx.x, tid = threadIdx.x;
    if (bid < 256) {
        int t = bid * 256 + tid;
        int w = t >> 14;
        int rem = t & 16383;                  // j*128 + k
        int j = rem >> 7, k = rem & 127;
        const float* src = (w == 0) ? wl2 : (w == 1) ? wr2 : (w == 2) ? wl3 : wr3;
        ((float*)g_w4)[w * 16384 + (k >> 2) * 512 + j * 4 + (k & 3)] = src[rem];
    } else {
        int t = (bid - 256) * 256 + tid;
        if (t < 2 * IN_CH * HID) {
            int m = t / (IN_CH * HID);
            int rem = t % (IN_CH * HID);
            int j = rem / IN_CH, k = rem % IN_CH;
            g_wt1[m * IN_CH * HID + k * HID + j] = (m == 0 ? wl1 : wr1)[rem];
        }
    }
}

// ---------------- prep B: dtype detection ----------------
__global__ void k_prep_d(const unsigned int* ei) {
    if (threadIdx.x == 0) {
        int all0 = 1;
        for (int i = 0; i < 16; i++)
            if (ei[2 * i + 1] != 0u) all0 = 0;
        g_idx64 = all0;
    }
}

// ---------------- per-graph CSR build ----------------
__global__ __launch_bounds__(1024) void k_csr(const void* ei) {
    __shared__ int cnt_s[N_PER];
    __shared__ int cur_s[N_PER];
    __shared__ int wsum[32];
    int g = blockIdx.x, t = threadIdx.x;
    int lane = t & 31, warp = t >> 5;
    int ebase = g * EPG, nbase = g * N_PER;
    int idx64 = g_idx64;

    cnt_s[t] = 0;
    __syncthreads();
    if (idx64) {
        const long long* p = (const long long*)ei;
#pragma unroll 4
        for (int i = t; i < EPG; i += 1024)
            atomicAdd(&cnt_s[(int)p[N_EDGE + ebase + i] - nbase], 1);
    } else {
        const int* p = (const int*)ei;
#pragma unroll 4
        for (int i = t; i < EPG; i += 1024)
            atomicAdd(&cnt_s[p[N_EDGE + ebase + i] - nbase], 1);
    }
    __syncthreads();
    int c = cnt_s[t], v = c;
#pragma unroll
    for (int o = 1; o < 32; o <<= 1) {
        int u = __shfl_up_sync(0xffffffffu, v, o);
        if (lane >= o) v += u;
    }
    if (lane == 31) wsum[warp] = v;
    __syncthreads();
    if (warp == 0) {
        int w = wsum[lane];
#pragma unroll
        for (int o = 1; o < 32; o <<= 1) {
            int u = __shfl_up_sync(0xffffffffu, w, o);
            if (lane >= o) w += u;
        }
        wsum[lane] = w;
    }
    __syncthreads();
    int start_local = v + (warp > 0 ? wsum[warp - 1] : 0) - c;
    g_rowstart[nbase + t] = ebase + start_local;
    g_cnt[nbase + t] = c;
    g_deginv[nbase + t] = c > 0 ? 1.0f / (float)c : 0.0f;
    cur_s[t] = start_local;
    __syncthreads();
    if (idx64) {
        const long long* p = (const long long*)ei;
#pragma unroll 4
        for (int i = t; i < EPG; i += 1024) {
            int s = (int)p[ebase + i], d = (int)p[N_EDGE + ebase + i] - nbase;
            g_csrc[ebase + atomicAdd(&cur_s[d], 1)] = s;
        }
    } else {
        const int* p = (const int*)ei;
#pragma unroll 4
        for (int i = t; i < EPG; i += 1024) {
            int s = p[ebase + i], d = p[N_EDGE + ebase + i] - nbase;
            g_csrc[ebase + atomicAdd(&cur_s[d], 1)] = s;
        }
    }
}

// ---------------- layer 1 fused: 8-deep MLP gather + dense ----------------
__global__ __launch_bounds__(256, 6) void k_layer1(
    const float* __restrict__ x, const float* __restrict__ b) {
    __shared__ float a_s[32 * IN_CH];
    __shared__ float x_s[32 * IN_CH];
    int nb = blockIdx.x * 32, tid = threadIdx.x;
    int warp = tid >> 5, lane = tid & 31;

    for (int i = tid; i < 32 * IN_CH; i += 256)
        x_s[i] = x[(size_t)(nb + i / IN_CH) * IN_CH + i % IN_CH];

    // gather: half-warps take even/odd edges, 4 loads in flight each (MLP 8/warp)
    int hw = lane >> 4;
    int ch = lane & 15;
    for (int q = 0; q < 4; q++) {
        int node = nb + warp * 4 + q;
        int start = g_rowstart[node];
        int deg = g_cnt[node];
        float a0 = 0.f, a1 = 0.f, a2 = 0.f, a3 = 0.f;
        if (ch < IN_CH) {
            int j = hw;
            for (; j + 6 < deg; j += 8) {
                a0 += x[(size_t)g_csrc[start + j] * IN_CH + ch];
                a1 += x[(size_t)g_csrc[start + j + 2] * IN_CH + ch];
                a2 += x[(size_t)g_csrc[start + j + 4] * IN_CH + ch];
                a3 += x[(size_t)g_csrc[start + j + 6] * IN_CH + ch];
            }
            for (; j < deg; j += 2)
                a0 += x[(size_t)g_csrc[start + j] * IN_CH + ch];
        }
        float acc = (a0 + a1) + (a2 + a3);
        acc += __shfl_down_sync(0xffffffffu, acc, 16);
        if (lane < IN_CH)
            a_s[(warp * 4 + q) * IN_CH + lane] = acc * g_deginv[node];
    }
    __syncthreads();

    int j = tid & 127, half = tid >> 7;
    const float* wlt = g_wt1 + j;
    const float* wrt = g_wt1 + IN_CH * HID + j;
    float acc[16], bj = b[j];
#pragma unroll
    for (int n = 0; n < 16; n++) acc[n] = bj;
    const float* as = a_s + half * 16 * IN_CH;
    const float* xs = x_s + half * 16 * IN_CH;
    for (int k = 0; k < IN_CH; k++) {
        float wlv = wlt[k * HID], wrv = wrt[k * HID];
#pragma unroll
        for (int n = 0; n < 16; n++)
            acc[n] += as[n * IN_CH + k] * wlv + xs[n * IN_CH + k] * wrv;
    }
    float* hout = (float*)g_hA;
#pragma unroll
    for (int n = 0; n < 16; n++)
        hout[(size_t)(nb + half * 16 + n) * HID + j] = fmaxf(acc[n], 0.0f);
}

// ---------------- fused SAGE layer (R13 config: 32-node CTA, 4 blk/SM, f32x2) -------
__global__ __launch_bounds__(256, 4) void k_layer(const float* __restrict__ b, int sel) {
    __shared__ float4 a_s4[32 * 32];
    __shared__ float4 p_s4[32 * 32];
    int nb = blockIdx.x * 32, tid = threadIdx.x;
    int warp = tid >> 5, lane = tid & 31;

    const float4* h4 = sel ? g_hB : g_hA;
    float* hout      = sel ? (float*)g_hA : (float*)g_hB;
    const float4* wl4 = g_w4 + sel * 8192;
    const float4* wr4 = wl4 + 4096;

#pragma unroll
    for (int i = 0; i < 4; i++)
        p_s4[tid + i * 256] = h4[(size_t)nb * 32 + tid + i * 256];

    // aggregation: warp handles 4 nodes; lane owns a float4 column; 8-way MLP
    for (int q = 0; q < 4; q++) {
        int node = nb + warp * 4 + q;
        int start = g_rowstart[node];
        int deg = g_cnt[node];
        float4 a0 = make_float4(0.f, 0.f, 0.f, 0.f);
        float4 a1 = a0, a2 = a0, a3 = a0, a4v = a0, a5 = a0, a6 = a0, a7 = a0;
        int j = 0;
        for (; j + 8 <= deg; j += 8) {
            float4 v0 = h4[(size_t)g_csrc[start + j] * 32 + lane];
            float4 v1 = h4[(size_t)g_csrc[start + j + 1] * 32 + lane];
            float4 v2 = h4[(size_t)g_csrc[start + j + 2] * 32 + lane];
            float4 v3 = h4[(size_t)g_csrc[start + j + 3] * 32 + lane];
            float4 v4 = h4[(size_t)g_csrc[start + j + 4] * 32 + lane];
            float4 v5 = h4[(size_t)g_csrc[start + j + 5] * 32 + lane];
            float4 v6 = h4[(size_t)g_csrc[start + j + 6] * 32 + lane];
            float4 v7 = h4[(size_t)g_csrc[start + j + 7] * 32 + lane];
            a0.x += v0.x; a0.y += v0.y; a0.z += v0.z; a0.w += v0.w;
            a1.x += v1.x; a1.y += v1.y; a1.z += v1.z; a1.w += v1.w;
            a2.x += v2.x; a2.y += v2.y; a2.z += v2.z; a2.w += v2.w;
            a3.x += v3.x; a3.y += v3.y; a3.z += v3.z; a3.w += v3.w;
            a4v.x += v4.x; a4v.y += v4.y; a4v.z += v4.z; a4v.w += v4.w;
            a5.x += v5.x; a5.y += v5.y; a5.z += v5.z; a5.w += v5.w;
            a6.x += v6.x; a6.y += v6.y; a6.z += v6.z; a6.w += v6.w;
            a7.x += v7.x; a7.y += v7.y; a7.z += v7.z; a7.w += v7.w;
        }
        for (; j < deg; j++) {
            float4 v0 = h4[(size_t)g_csrc[start + j] * 32 + lane];
            a0.x += v0.x; a0.y += v0.y; a0.z += v0.z; a0.w += v0.w;
        }
        float dv = g_deginv[node];
        a0.x = (a0.x + a1.x + a2.x + a3.x + a4v.x + a5.x + a6.x + a7.x) * dv;
        a0.y = (a0.y + a1.y + a2.y + a3.y + a4v.y + a5.y + a6.y + a7.y) * dv;
        a0.z = (a0.z + a1.z + a2.z + a3.z + a4v.z + a5.z + a6.z + a7.z) * dv;
        a0.w = (a0.w + a1.w + a2.w + a3.w + a4v.w + a5.w + a6.w + a7.w) * dv;
        a_s4[(warp * 4 + q) * 32 + lane] = a0;
    }
    __syncthreads();

    // dense: 2 output channels {jj, jj+64} x 8 nodes, f32x2, two passes
    int jj = tid & 63;
    int q  = tid >> 6;
    u64 accA2[8], accB2[8];
#pragma unroll
    for (int n = 0; n < 8; n++) { accA2[n] = 0ull; accB2[n] = 0ull; }

    const float4* a4 = a_s4 + q * 8 * 32;
    const float4* p4 = p_s4 + q * 8 * 32;
    for (int kc = 0; kc < 32; kc++) {
        F4 wA, wB;
        wA.f = wl4[kc * 128 + jj];
        wB.f = wl4[kc * 128 + jj + 64];
#pragma unroll
        for (int n = 0; n < 8; n++) {
            F4 av; av.f = a4[n * 32 + kc];
            FMA2(accA2[n], av.d[0], wA.d[0]);
            FMA2(accA2[n], av.d[1], wA.d[1]);
            FMA2(accB2[n], av.d[0], wB.d[0]);
            FMA2(accB2[n], av.d[1], wB.d[1]);
        }
    }
    for (int kc = 0; kc < 32; kc++) {
        F4 wA, wB;
        wA.f = wr4[kc * 128 + jj];
        wB.f = wr4[kc * 128 + jj + 64];
#pragma unroll
        for (int n = 0; n < 8; n++) {
            F4 pv; pv.f = p4[n * 32 + kc];
            FMA2(accA2[n], pv.d[0], wA.d[0]);
            FMA2(accA2[n], pv.d[1], wA.d[1]);
            FMA2(accB2[n], pv.d[0], wB.d[0]);
            FMA2(accB2[n], pv.d[1], wB.d[1]);
        }
    }

    float bA = b[jj], bB = b[jj + 64];
#pragma unroll
    for (int n = 0; n < 8; n++) {
        float2 rA = *(float2*)&accA2[n];
        float2 rB = *(float2*)&accB2[n];
        size_t row = (size_t)(nb + q * 8 + n) * HID;
        hout[row + jj]      = fmaxf(bA + rA.x + rA.y, 0.0f);
        hout[row + jj + 64] = fmaxf(bB + rB.x + rB.y, 0.0f);
    }
}

// ---------------- fused top-k + conv1d + lin1 + lin2 ----------------
#define TS_PAD 32
__global__ __launch_bounds__(256) void k_topk_head(
    const float* __restrict__ conv_w, const float* __restrict__ conv_b,
    const float* __restrict__ lin1_w, const float* __restrict__ lin1_b,
    const float* __restrict__ lin2_w, const float* __restrict__ lin2_b,
    float* __restrict__ out) {
    __shared__ float vals[N_PER];
    __shared__ unsigned long long wred[8];
    __shared__ int sel[K_POOL];
    __shared__ float top_ts[HID * TS_PAD];
    __shared__ float feat[FEAT_LEN];
    __shared__ float y1[HID];
    const float* h = (const float*)g_hA;
    int g = blockIdx.x, tid = threadIdx.x;
    int warp = tid >> 5, lane = tid & 31;
    size_t base = (size_t)g * N_PER;

    for (int i = tid; i < N_PER; i += 256)
        vals[i] = h[(base + i) * HID + (HID - 1)];
    __syncthreads();
    for (int t = 0; t < K_POOL; t++) {
        unsigned long long best = 0ull;
        for (int i = tid; i < N_PER; i += 256) {
            float v = vals[i];
            if (v >= 0.0f) {
                unsigned long long key =
                    ((unsigned long long)__float_as_uint(v) << 32) |
                    (unsigned long long)(0xFFFFFFFFu - (unsigned)i);
                if (key > best) best = key;
            }
        }
#pragma unroll
        for (int o = 16; o > 0; o >>= 1) {
            unsigned long long other = __shfl_down_sync(0xffffffffu, best, o);
            if (other > best) best = other;
        }
        if (lane == 0) wred[warp] = best;
        __syncthreads();
        if (tid == 0) {
            unsigned long long b0 = wred[0];
#pragma unroll
            for (int w = 1; w < 8; w++)
                if (wred[w] > b0) b0 = wred[w];
            int idx = (int)(0xFFFFFFFFu - (unsigned)(b0 & 0xFFFFFFFFull));
            sel[t] = idx;
            vals[idx] = -1.0f;
        }
        __syncthreads();
    }
    for (int i = tid; i < K_POOL * HID; i += 256) {
        int t = i / HID, c = i % HID;
        top_ts[c * TS_PAD + t] = h[(base + sel[t]) * HID + c];
    }
    __syncthreads();
    for (int m = tid; m < FEAT_LEN; m += 256) {
        int o = m / CONV_T, t = m % CONV_T;
        float acc = conv_b[o];
        const float* wrow = conv_w + (size_t)o * HID * 5;
        for (int c = 0; c < HID; c++) {
            const float* w5 = wrow + c * 5;
            const float* ts = top_ts + c * TS_PAD + t;
#pragma unroll
            for (int tau = 0; tau < 5; tau++)
                acc += ts[tau] * w5[tau];
        }
        feat[m] = fmaxf(acc, 0.0f);
    }
    __syncthreads();
    if (tid < HID) {
        float acc = lin1_b[tid];
        const float* wrow = lin1_w + (size_t)tid * FEAT_LEN;
        for (int k = 0; k < FEAT_LEN; k++) acc += feat[k] * wrow[k];
        y1[tid] = fmaxf(acc, 0.0f);
    }
    __syncthreads();
    if (tid < 4) {
        float acc = lin2_b[tid];
        const float* wrow = lin2_w + tid * HID;
        for (int k = 0; k < HID; k++) acc += y1[k] * wrow[k];
        out[g * 4 + tid] = acc;
    }
}

// ---------------- launcher (k_layer1 is the 4th launch -> profiled) ----------------
extern "C" void kernel_launch(void* const* d_in, const int* in_sizes, int n_in,
                              void* d_out, int out_size) {
    const float* x      = (const float*)d_in[0];
    const void*  ei     = d_in[1];
    const float* w_l1   = (const float*)d_in[3];
    const float* b_l1   = (const float*)d_in[4];
    const float* w_r1   = (const float*)d_in[5];
    const float* w_l2   = (const float*)d_in[6];
    const float* b_l2   = (const float*)d_in[7];
    const float* w_r2   = (const float*)d_in[8];
    const float* w_l3   = (const float*)d_in[9];
    const float* b_l3   = (const float*)d_in[10];
    const float* w_r3   = (const float*)d_in[11];
    const float* conv_w = (const float*)d_in[12];
    const float* conv_b = (const float*)d_in[13];
    const float* lin1_w = (const float*)d_in[14];
    const float* lin1_b = (const float*)d_in[15];
    const float* lin2_w = (const float*)d_in[16];
    const float* lin2_b = (const float*)d_in[17];
    float* out = (float*)d_out;

    k_prep_w<<<270, 256>>>(w_l1, w_r1, w_l2, w_r2, w_l3, w_r3);     // 1
    k_prep_d<<<1, 32>>>((const unsigned int*)ei);                    // 2
    k_csr<<<B_GRAPHS, 1024>>>(ei);                                   // 3
    k_layer1<<<N_NODES / 32, 256>>>(x, b_l1);                        // 4 <- profiled
    k_layer<<<N_NODES / 32, 256>>>(b_l2, 0);                         // 5
    k_layer<<<N_NODES / 32, 256>>>(b_l3, 1);                         // 6
    k_topk_head<<<B_GRAPHS, 256>>>(conv_w, conv_b, lin1_w, lin1_b,
                                   lin2_w, lin2_b, out);             // 7
}

// round 16
// speedup vs baseline: 1.1338x; 1.0110x over previous
#include <cuda_runtime.h>
#include <cuda_bf16.h>
#include <cstdint>

#define N_NODES  131072
#define N_PER    1024
#define B_GRAPHS 128
#define N_EDGE   2097152
#define EPG      (N_EDGE / B_GRAPHS)
#define HID      128
#define IN_CH    14
#define K_POOL   30
#define CONV_T   26
#define FEAT_LEN 832

typedef unsigned long long u64;
#define FMA2(acc, a, b) \
    asm("fma.rn.f32x2 %0, %1, %2, %0;" : "+l"(acc) : "l"(a), "l"(b))
union F4 { float4 f; u64 d[2]; };

// ---------------- scratch (device-only) ----------------
__device__ int    g_cnt[N_NODES];
__device__ int    g_rowstart[N_NODES];
__device__ float  g_deginv[N_NODES];
__device__ int    g_csrc[N_EDGE];
__device__ float4 g_hA[N_NODES * HID / 4];
__device__ float4 g_hB[N_NODES * HID / 4];
__device__ float4 g_w4[4 * 32 * HID];      // chunk-packed k-major wl2,wr2,wl3,wr3
__device__ float  g_wt1[2 * IN_CH * HID];  // k-major layer1 weights
__device__ int    g_idx64;

// ---------------- prep (fused): weight repack + dtype detect ----------------
__global__ __launch_bounds__(256) void k_prep(
    const unsigned int* ei,
    const float* __restrict__ wl1, const float* __restrict__ wr1,
    const float* __restrict__ wl2, const float* __restrict__ wr2,
    const float* __restrict__ wl3, const float* __restrict__ wr3) {
    int bid = blockIdx.x, tid = threadIdx.x;
    if (bid < 256) {
        int t = bid * 256 + tid;
        int w = t >> 14;
        int rem = t & 16383;                  // j*128 + k
        int j = rem >> 7, k = rem & 127;
        const float* src = (w == 0) ? wl2 : (w == 1) ? wr2 : (w == 2) ? wl3 : wr3;
        ((float*)g_w4)[w * 16384 + (k >> 2) * 512 + j * 4 + (k & 3)] = src[rem];
    } else if (bid < 270) {
        int t = (bid - 256) * 256 + tid;
        if (t < 2 * IN_CH * HID) {
            int m = t / (IN_CH * HID);
            int rem = t % (IN_CH * HID);
            int j = rem / IN_CH, k = rem % IN_CH;
            g_wt1[m * IN_CH * HID + k * HID + j] = (m == 0 ? wl1 : wr1)[rem];
        }
    } else if (tid == 0) {
        int all0 = 1;
        for (int i = 0; i < 16; i++)
            if (ei[2 * i + 1] != 0u) all0 = 0;
        g_idx64 = all0;
    }
}

// ---------------- per-graph CSR build ----------------
__global__ __launch_bounds__(1024) void k_csr(const void* ei) {
    __shared__ int cnt_s[N_PER];
    __shared__ int cur_s[N_PER];
    __shared__ int wsum[32];
    int g = blockIdx.x, t = threadIdx.x;
    int lane = t & 31, warp = t >> 5;
    int ebase = g * EPG, nbase = g * N_PER;
    int idx64 = g_idx64;

    cnt_s[t] = 0;
    __syncthreads();
    if (idx64) {
        const long long* p = (const long long*)ei;
#pragma unroll 4
        for (int i = t; i < EPG; i += 1024)
            atomicAdd(&cnt_s[(int)p[N_EDGE + ebase + i] - nbase], 1);
    } else {
        const int* p = (const int*)ei;
#pragma unroll 4
        for (int i = t; i < EPG; i += 1024)
            atomicAdd(&cnt_s[p[N_EDGE + ebase + i] - nbase], 1);
    }
    __syncthreads();
    int c = cnt_s[t], v = c;
#pragma unroll
    for (int o = 1; o < 32; o <<= 1) {
        int u = __shfl_up_sync(0xffffffffu, v, o);
        if (lane >= o) v += u;
    }
    if (lane == 31) wsum[warp] = v;
    __syncthreads();
    if (warp == 0) {
        int w = wsum[lane];
#pragma unroll
        for (int o = 1; o < 32; o <<= 1) {
            int u = __shfl_up_sync(0xffffffffu, w, o);
            if (lane >= o) w += u;
        }
        wsum[lane] = w;
    }
    __syncthreads();
    int start_local = v + (warp > 0 ? wsum[warp - 1] : 0) - c;
    g_rowstart[nbase + t] = ebase + start_local;
    g_cnt[nbase + t] = c;
    g_deginv[nbase + t] = c > 0 ? 1.0f / (float)c : 0.0f;
    cur_s[t] = start_local;
    __syncthreads();
    if (idx64) {
        const long long* p = (const long long*)ei;
#pragma unroll 4
        for (int i = t; i < EPG; i += 1024) {
            int s = (int)p[ebase + i], d = (int)p[N_EDGE + ebase + i] - nbase;
            g_csrc[ebase + atomicAdd(&cur_s[d], 1)] = s;
        }
    } else {
        const int* p = (const int*)ei;
#pragma unroll 4
        for (int i = t; i < EPG; i += 1024) {
            int s = p[ebase + i], d = p[N_EDGE + ebase + i] - nbase;
            g_csrc[ebase + atomicAdd(&cur_s[d], 1)] = s;
        }
    }
}

// ---------------- layer 1 fused: float2 4-edge gather + dense ----------------
// Gather lanes: slot = lane>>3 (4 edge slots), cp = lane&7 (channel pair, cp<7).
// One warp load instruction covers 4 edges x 56B (vs 2 edges before).
__global__ __launch_bounds__(256, 6) void k_layer1(
    const float* __restrict__ x, const float* __restrict__ b) {
    __shared__ float a_s[32 * IN_CH];
    __shared__ float x_s[32 * IN_CH];
    int nb = blockIdx.x * 32, tid = threadIdx.x;
    int warp = tid >> 5, lane = tid & 31;

    for (int i = tid; i < 32 * IN_CH; i += 256)
        x_s[i] = x[(size_t)(nb + i / IN_CH) * IN_CH + i % IN_CH];

    const float2* x2 = (const float2*)x;   // 7 float2 per row (56B, 8B-aligned)
    int slot = lane >> 3;
    int cp = lane & 7;
    for (int q = 0; q < 4; q++) {
        int node = nb + warp * 4 + q;
        int start = g_rowstart[node];
        int deg = g_cnt[node];
        float2 acc = make_float2(0.f, 0.f);
        if (cp < 7) {
            for (int j = slot; j < deg; j += 4) {
                float2 v = x2[(size_t)g_csrc[start + j] * 7 + cp];
                acc.x += v.x;
                acc.y += v.y;
            }
        }
        // reduce across the 4 slots (lanes differing by 8, 16)
        acc.x += __shfl_down_sync(0xffffffffu, acc.x, 16);
        acc.y += __shfl_down_sync(0xffffffffu, acc.y, 16);
        acc.x += __shfl_down_sync(0xffffffffu, acc.x, 8);
        acc.y += __shfl_down_sync(0xffffffffu, acc.y, 8);
        if (lane < 7) {
            float dv = g_deginv[node];
            a_s[(warp * 4 + q) * IN_CH + 2 * lane]     = acc.x * dv;
            a_s[(warp * 4 + q) * IN_CH + 2 * lane + 1] = acc.y * dv;
        }
    }
    __syncthreads();

    int j = tid & 127, half = tid >> 7;
    const float* wlt = g_wt1 + j;
    const float* wrt = g_wt1 + IN_CH * HID + j;
    float acc[16], bj = b[j];
#pragma unroll
    for (int n = 0; n < 16; n++) acc[n] = bj;
    const float* as = a_s + half * 16 * IN_CH;
    const float* xs = x_s + half * 16 * IN_CH;
    for (int k = 0; k < IN_CH; k++) {
        float wlv = wlt[k * HID], wrv = wrt[k * HID];
#pragma unroll
        for (int n = 0; n < 16; n++)
            acc[n] += as[n * IN_CH + k] * wlv + xs[n * IN_CH + k] * wrv;
    }
    float* hout = (float*)g_hA;
#pragma unroll
    for (int n = 0; n < 16; n++)
        hout[(size_t)(nb + half * 16 + n) * HID + j] = fmaxf(acc[n], 0.0f);
}

// ---------------- fused SAGE layer (R13 config: 32-node CTA, 4 blk/SM, f32x2) -------
__global__ __launch_bounds__(256, 4) void k_layer(const float* __restrict__ b, int sel) {
    __shared__ float4 a_s4[32 * 32];
    __shared__ float4 p_s4[32 * 32];
    int nb = blockIdx.x * 32, tid = threadIdx.x;
    int warp = tid >> 5, lane = tid & 31;

    const float4* h4 = sel ? g_hB : g_hA;
    float* hout      = sel ? (float*)g_hA : (float*)g_hB;
    const float4* wl4 = g_w4 + sel * 8192;
    const float4* wr4 = wl4 + 4096;

#pragma unroll
    for (int i = 0; i < 4; i++)
        p_s4[tid + i * 256] = h4[(size_t)nb * 32 + tid + i * 256];

    for (int q = 0; q < 4; q++) {
        int node = nb + warp * 4 + q;
        int start = g_rowstart[node];
        int deg = g_cnt[node];
        float4 a0 = make_float4(0.f, 0.f, 0.f, 0.f);
        float4 a1 = a0, a2 = a0, a3 = a0, a4v = a0, a5 = a0, a6 = a0, a7 = a0;
        int j = 0;
        for (; j + 8 <= deg; j += 8) {
            float4 v0 = h4[(size_t)g_csrc[start + j] * 32 + lane];
            float4 v1 = h4[(size_t)g_csrc[start + j + 1] * 32 + lane];
            float4 v2 = h4[(size_t)g_csrc[start + j + 2] * 32 + lane];
            float4 v3 = h4[(size_t)g_csrc[start + j + 3] * 32 + lane];
            float4 v4 = h4[(size_t)g_csrc[start + j + 4] * 32 + lane];
            float4 v5 = h4[(size_t)g_csrc[start + j + 5] * 32 + lane];
            float4 v6 = h4[(size_t)g_csrc[start + j + 6] * 32 + lane];
            float4 v7 = h4[(size_t)g_csrc[start + j + 7] * 32 + lane];
            a0.x += v0.x; a0.y += v0.y; a0.z += v0.z; a0.w += v0.w;
            a1.x += v1.x; a1.y += v1.y; a1.z += v1.z; a1.w += v1.w;
            a2.x += v2.x; a2.y += v2.y; a2.z += v2.z; a2.w += v2.w;
            a3.x += v3.x; a3.y += v3.y; a3.z += v3.z; a3.w += v3.w;
            a4v.x += v4.x; a4v.y += v4.y; a4v.z += v4.z; a4v.w += v4.w;
            a5.x += v5.x; a5.y += v5.y; a5.z += v5.z; a5.w += v5.w;
            a6.x += v6.x; a6.y += v6.y; a6.z += v6.z; a6.w += v6.w;
            a7.x += v7.x; a7.y += v7.y; a7.z += v7.z; a7.w += v7.w;
        }
        for (; j < deg; j++) {
            float4 v0 = h4[(size_t)g_csrc[start + j] * 32 + lane];
            a0.x += v0.x; a0.y += v0.y; a0.z += v0.z; a0.w += v0.w;
        }
        float dv = g_deginv[node];
        a0.x = (a0.x + a1.x + a2.x + a3.x + a4v.x + a5.x + a6.x + a7.x) * dv;
        a0.y = (a0.y + a1.y + a2.y + a3.y + a4v.y + a5.y + a6.y + a7.y) * dv;
        a0.z = (a0.z + a1.z + a2.z + a3.z + a4v.z + a5.z + a6.z + a7.z) * dv;
        a0.w = (a0.w + a1.w + a2.w + a3.w + a4v.w + a5.w + a6.w + a7.w) * dv;
        a_s4[(warp * 4 + q) * 32 + lane] = a0;
    }
    __syncthreads();

    int jj = tid & 63;
    int q  = tid >> 6;
    u64 accA2[8], accB2[8];
#pragma unroll
    for (int n = 0; n < 8; n++) { accA2[n] = 0ull; accB2[n] = 0ull; }

    const float4* a4 = a_s4 + q * 8 * 32;
    const float4* p4 = p_s4 + q * 8 * 32;
    for (int kc = 0; kc < 32; kc++) {
        F4 wA, wB;
        wA.f = wl4[kc * 128 + jj];
        wB.f = wl4[kc * 128 + jj + 64];
#pragma unroll
        for (int n = 0; n < 8; n++) {
            F4 av; av.f = a4[n * 32 + kc];
            FMA2(accA2[n], av.d[0], wA.d[0]);
            FMA2(accA2[n], av.d[1], wA.d[1]);
            FMA2(accB2[n], av.d[0], wB.d[0]);
            FMA2(accB2[n], av.d[1], wB.d[1]);
        }
    }
    for (int kc = 0; kc < 32; kc++) {
        F4 wA, wB;
        wA.f = wr4[kc * 128 + jj];
        wB.f = wr4[kc * 128 + jj + 64];
#pragma unroll
        for (int n = 0; n < 8; n++) {
            F4 pv; pv.f = p4[n * 32 + kc];
            FMA2(accA2[n], pv.d[0], wA.d[0]);
            FMA2(accA2[n], pv.d[1], wA.d[1]);
            FMA2(accB2[n], pv.d[0], wB.d[0]);
            FMA2(accB2[n], pv.d[1], wB.d[1]);
        }
    }

    float bA = b[jj], bB = b[jj + 64];
#pragma unroll
    for (int n = 0; n < 8; n++) {
        float2 rA = *(float2*)&accA2[n];
        float2 rB = *(float2*)&accB2[n];
        size_t row = (size_t)(nb + q * 8 + n) * HID;
        hout[row + jj]      = fmaxf(bA + rA.x + rA.y, 0.0f);
        hout[row + jj + 64] = fmaxf(bB + rB.x + rB.y, 0.0f);
    }
}

// ---------------- fused top-k + conv1d + lin1 + lin2 ----------------
#define TS_PAD 32
__global__ __launch_bounds__(256) void k_topk_head(
    const float* __restrict__ conv_w, const float* __restrict__ conv_b,
    const float* __restrict__ lin1_w, const float* __restrict__ lin1_b,
    const float* __restrict__ lin2_w, const float* __restrict__ lin2_b,
    float* __restrict__ out) {
    __shared__ float vals[N_PER];
    __shared__ unsigned long long wred[8];
    __shared__ int sel[K_POOL];
    __shared__ float top_ts[HID * TS_PAD];
    __shared__ float feat[FEAT_LEN];
    __shared__ float y1[HID];
    const float* h = (const float*)g_hA;
    int g = blockIdx.x, tid = threadIdx.x;
    int warp = tid >> 5, lane = tid & 31;
    size_t base = (size_t)g * N_PER;

    for (int i = tid; i < N_PER; i += 256)
        vals[i] = h[(base + i) * HID + (HID - 1)];
    __syncthreads();
    for (int t = 0; t < K_POOL; t++) {
        unsigned long long best = 0ull;
        for (int i = tid; i < N_PER; i += 256) {
            float v = vals[i];
            if (v >= 0.0f) {
                unsigned long long key =
                    ((unsigned long long)__float_as_uint(v) << 32) |
                    (unsigned long long)(0xFFFFFFFFu - (unsigned)i);
                if (key > best) best = key;
            }
        }
#pragma unroll
        for (int o = 16; o > 0; o >>= 1) {
            unsigned long long other = __shfl_down_sync(0xffffffffu, best, o);
            if (other > best) best = other;
        }
        if (lane == 0) wred[warp] = best;
        __syncthreads();
        if (tid == 0) {
            unsigned long long b0 = wred[0];
#pragma unroll
            for (int w = 1; w < 8; w++)
                if (wred[w] > b0) b0 = wred[w];
            int idx = (int)(0xFFFFFFFFu - (unsigned)(b0 & 0xFFFFFFFFull));
            sel[t] = idx;
            vals[idx] = -1.0f;
        }
        __syncthreads();
    }
    for (int i = tid; i < K_POOL * HID; i += 256) {
        int t = i / HID, c = i % HID;
        top_ts[c * TS_PAD + t] = h[(base + sel[t]) * HID + c];
    }
    __syncthreads();
    for (int m = tid; m < FEAT_LEN; m += 256) {
        int o = m / CONV_T, t = m % CONV_T;
        float acc = conv_b[o];
        const float* wrow = conv_w + (size_t)o * HID * 5;
        for (int c = 0; c < HID; c++) {
            const float* w5 = wrow + c * 5;
            const float* ts = top_ts + c * TS_PAD + t;
#pragma unroll
            for (int tau = 0; tau < 5; tau++)
                acc += ts[tau] * w5[tau];
        }
        feat[m] = fmaxf(acc, 0.0f);
    }
    __syncthreads();
    if (tid < HID) {
        float acc = lin1_b[tid];
        const float* wrow = lin1_w + (size_t)tid * FEAT_LEN;
        for (int k = 0; k < FEAT_LEN; k++) acc += feat[k] * wrow[k];
        y1[tid] = fmaxf(acc, 0.0f);
    }
    __syncthreads();
    if (tid < 4) {
        float acc = lin2_b[tid];
        const float* wrow = lin2_w + tid * HID;
        for (int k = 0; k < HID; k++) acc += y1[k] * wrow[k];
        out[g * 4 + tid] = acc;
    }
}

// ---------------- launcher ----------------
extern "C" void kernel_launch(void* const* d_in, const int* in_sizes, int n_in,
                              void* d_out, int out_size) {
    const float* x      = (const float*)d_in[0];
    const void*  ei     = d_in[1];
    const float* w_l1   = (const float*)d_in[3];
    const float* b_l1   = (const float*)d_in[4];
    const float* w_r1   = (const float*)d_in[5];
    const float* w_l2   = (const float*)d_in[6];
    const float* b_l2   = (const float*)d_in[7];
    const float* w_r2   = (const float*)d_in[8];
    const float* w_l3   = (const float*)d_in[9];
    const float* b_l3   = (const float*)d_in[10];
    const float* w_r3   = (const float*)d_in[11];
    const float* conv_w = (const float*)d_in[12];
    const float* conv_b = (const float*)d_in[13];
    const float* lin1_w = (const float*)d_in[14];
    const float* lin1_b = (const float*)d_in[15];
    const float* lin2_w = (const float*)d_in[16];
    const float* lin2_b = (const float*)d_in[17];
    float* out = (float*)d_out;

    k_prep<<<271, 256>>>((const unsigned int*)ei, w_l1, w_r1, w_l2, w_r2, w_l3, w_r3);
    k_csr<<<B_GRAPHS, 1024>>>(ei);
    k_layer1<<<N_NODES / 32, 256>>>(x, b_l1);
    k_layer<<<N_NODES / 32, 256>>>(b_l2, 0);   // 4th launch -> profiled
    k_layer<<<N_NODES / 32, 256>>>(b_l3, 1);
    k_topk_head<<<B_GRAPHS, 256>>>(conv_w, conv_b, lin1_w, lin1_b,
                                   lin2_w, lin2_b, out);
}